// round 4
// baseline (speedup 1.0000x reference)
#include <cuda_runtime.h>

// LIF scan: v = v + (x - v)*0.5; s = (v >= 1); v = s ? 0 : v
// x: [B=64, T=200, N=4096] fp32 -> spikes same shape.
// Each thread owns 4 consecutive n (one float4) for one b, walks T serially.
// Depth-2 software pipeline over groups of 8 timesteps: groups g+1 and g+2
// are in flight (up to 16 LDG.128 outstanding per thread) while the serial
// per-step dependency chain of group g executes, keeping the DRAM read
// stream continuous. Streaming cache hints (__ldcs/__stcs): data touched once.

#define LIF_B 64
#define LIF_T 200
#define LIF_N 4096
#define NV (LIF_N / 4)      // 1024 float4 per (b, t) row
#define G 8                 // timesteps per group
#define NGROUP (LIF_T / G)  // 25

__device__ __forceinline__ void lif_step(float& v, float xx, float& s) {
    v = v + (xx - v) * 0.5f;          // exact match to ref op order (x0.5 exact)
    bool fire = (v >= 1.0f);
    s = fire ? 1.0f : 0.0f;
    v = fire ? 0.0f : v;
}

__device__ __forceinline__ void load_group(const float4* __restrict__ xp,
                                           float4 (&xr)[G]) {
    #pragma unroll
    for (int i = 0; i < G; i++) xr[i] = __ldcs(xp + i * NV);
}

__device__ __forceinline__ void process_group(float4& v, const float4 (&xr)[G],
                                              float4* __restrict__ op) {
    #pragma unroll
    for (int i = 0; i < G; i++) {
        float4 s;
        lif_step(v.x, xr[i].x, s.x);
        lif_step(v.y, xr[i].y, s.y);
        lif_step(v.z, xr[i].z, s.z);
        lif_step(v.w, xr[i].w, s.w);
        __stcs(op + i * NV, s);
    }
}

__global__ __launch_bounds__(64)
void lif_kernel(const float4* __restrict__ x, float4* __restrict__ out) {
    int idx = blockIdx.x * blockDim.x + threadIdx.x;   // 0 .. B*NV-1
    int b   = idx >> 10;          // / NV (NV = 1024)
    int n4  = idx & (NV - 1);

    size_t base = (size_t)b * LIF_T * NV + n4;
    const float4* xp = x + base;       // load cursor (group to load next)
    float4*       op = out + base;     // store cursor (group being processed)

    float4 v = make_float4(0.f, 0.f, 0.f, 0.f);
    float4 xa[G], xb[G], xc[G];

    // Prologue: groups 0 and 1 in flight.
    load_group(xp, xa);  xp += G * NV;
    load_group(xp, xb);  xp += G * NV;

    // Steady state: 7 triple-iterations cover groups 0..20,
    // loading groups 2..22 (always 2 groups ahead of the one computed).
    #pragma unroll 1
    for (int gg = 0; gg < 7; gg++) {
        load_group(xp, xc);  xp += G * NV;
        process_group(v, xa, op);  op += G * NV;

        load_group(xp, xa);  xp += G * NV;
        process_group(v, xb, op);  op += G * NV;

        load_group(xp, xb);  xp += G * NV;
        process_group(v, xc, op);  op += G * NV;
    }
    // After loop: processed 0..20 (A holds g21, B holds g22).
    load_group(xp, xc);  xp += G * NV;          // g23
    process_group(v, xa, op);  op += G * NV;    // g21

    load_group(xp, xa);                          // g24
    process_group(v, xb, op);  op += G * NV;    // g22

    process_group(v, xc, op);  op += G * NV;    // g23
    process_group(v, xa, op);                    // g24
}

extern "C" void kernel_launch(void* const* d_in, const int* in_sizes, int n_in,
                              void* d_out, int out_size) {
    const float* x = (const float*)d_in[0];
    // d_in[1] = threshold param, unused by the reference forward
    float* out = (float*)d_out;

    const int total_threads = LIF_B * NV;   // 65536
    const int block = 64;
    lif_kernel<<<total_threads / block, block>>>(
        (const float4*)x, (float4*)out);
}

// round 7
// speedup vs baseline: 1.0894x; 1.0894x over previous
#include <cuda_runtime.h>

// LIF scan: v = v + (x - v)*0.5; s = (v >= 1); v = s ? 0 : v
// x: [B=64, T=200, N=4096] fp32 -> spikes same shape.
//
// R5: R3's proven depth-1 pipeline, single change: float2 granularity
// (2 elements/thread) -> 131072 threads, ~27.7 warps/SM (2x R3 occupancy).
// More warps fill the DRAM duty-cycle holes left while each warp runs its
// serial 8-step dependency chain; per-thread register footprint stays low
// (~16 payload regs) so the compiler can front-batch the 8 loads (MLP_p1=8).

#define LIF_B 64
#define LIF_T 200
#define LIF_N 4096
#define NV2 (LIF_N / 2)      // 2048 float2 per (b, t) row
#define G 8                  // timesteps per group
#define NGROUP (LIF_T / G)   // 25

__device__ __forceinline__ void lif_step(float& v, float xx, float& s) {
    v = v + (xx - v) * 0.5f;          // exact match to ref op order (x0.5 exact)
    bool fire = (v >= 1.0f);
    s = fire ? 1.0f : 0.0f;
    v = fire ? 0.0f : v;
}

__device__ __forceinline__ void load_group(const float2* __restrict__ xp,
                                           float2 (&xr)[G]) {
    #pragma unroll
    for (int i = 0; i < G; i++) xr[i] = __ldg(xp + i * NV2);
}

__device__ __forceinline__ void process_group(float2& v, const float2 (&xr)[G],
                                              float2* __restrict__ op) {
    #pragma unroll
    for (int i = 0; i < G; i++) {
        float2 s;
        lif_step(v.x, xr[i].x, s.x);
        lif_step(v.y, xr[i].y, s.y);
        op[i * NV2] = s;
    }
}

__global__ __launch_bounds__(64)
void lif_kernel(const float2* __restrict__ x, float2* __restrict__ out) {
    int idx = blockIdx.x * blockDim.x + threadIdx.x;   // 0 .. B*NV2-1
    int b   = idx >> 11;          // / NV2 (NV2 = 2048)
    int n2  = idx & (NV2 - 1);

    size_t base = (size_t)b * LIF_T * NV2 + n2;
    const float2* xp = x + base;
    float2*       op = out + base;

    float2 v = make_float2(0.f, 0.f);
    float2 xa[G], xb[G];

    // prologue: load group 0
    load_group(xp, xa);

    // 24 groups in 12 double-iterations; each half prefetches the next group
    // before touching the serial compute chain of the current one.
    #pragma unroll 1
    for (int gg = 0; gg < (NGROUP - 1) / 2; gg++) {
        load_group(xp + G * NV2, xb);        // prefetch group 2gg+1
        process_group(v, xa, op);            // compute+store group 2gg
        xp += G * NV2; op += G * NV2;

        load_group(xp + G * NV2, xa);        // prefetch group 2gg+2
        process_group(v, xb, op);            // compute+store group 2gg+1
        xp += G * NV2; op += G * NV2;
    }

    // epilogue: group 24 (already loaded into xa)
    process_group(v, xa, op);
}

extern "C" void kernel_launch(void* const* d_in, const int* in_sizes, int n_in,
                              void* d_out, int out_size) {
    const float* x = (const float*)d_in[0];
    // d_in[1] = threshold param, unused by the reference forward
    float* out = (float*)d_out;

    const int total_threads = LIF_B * NV2;   // 131072
    const int block = 64;
    lif_kernel<<<total_threads / block, block>>>(
        (const float2*)x, (float2*)out);
}